// round 5
// baseline (speedup 1.0000x reference)
#include <cuda_runtime.h>
#include <math.h>

#define FULL 0xFFFFFFFFu
#define T_LEN 2048
#define CHUNKS 16          // 16 chunks x 128 elems = 2048
#define WARPS_PER_BLOCK 8

__global__ __launch_bounds__(256, 4)
void scpp_kernel(const float* __restrict__ event_times,
                 const float* __restrict__ input_mask,
                 const float* __restrict__ t0p,
                 const float* __restrict__ t1p,
                 const float* __restrict__ mup,
                 const float* __restrict__ betap,
                 float* __restrict__ out)
{
    const int lane = threadIdx.x & 31;
    const int wid  = threadIdx.x >> 5;
    const int row  = blockIdx.x * WARPS_PER_BLOCK + wid;

    const float mu   = log1pf(expf(__ldg(mup)));
    const float beta = log1pf(expf(__ldg(betap)));
    const float t0   = __ldg(t0p);
    const float t1   = __ldg(t1p);

    const size_t rbase = (size_t)row * T_LEN;
    const float4* ev = reinterpret_cast<const float4*>(event_times + rbase);
    const float4* mk = reinterpret_cast<const float4*>(input_mask  + rbase);

    float sumt = 0.f;     // sum mask * t
    float sumidx = 0.f;   // sum mask * index   (exact: integer-valued floats < 2^24)
    float S = 0.f;        // sum masked exp(mu*t - beta*k)
    float T = 0.f;        // running masked count (warp-uniform, exact)

    #pragma unroll
    for (int i = 0; i < CHUNKS; i++) {
        // coalesced: warp covers 512 contiguous bytes per LDG.128
        const float4 e = ev[lane + 32 * i];
        const float4 m = mk[lane + 32 * i];

        // masks are exactly 0.0f / 1.0f
        const float cnt = (m.x + m.y) + (m.z + m.w);

        sumt = fmaf(m.x, e.x, sumt);
        sumt = fmaf(m.y, e.y, sumt);
        sumt = fmaf(m.z, e.z, sumt);
        sumt = fmaf(m.w, e.w, sumt);

        // sum mask*idx over the 4 elems = cnt*base + (m.y + 2*m.z + 3*m.w)
        const float base = (float)(128 * i + 4 * lane);
        sumidx = fmaf(cnt, base, sumidx);
        sumidx += fmaf(3.f, m.w, fmaf(2.f, m.z, m.y));

        // intra-warp inclusive scan of cnt (cross-chunk prefix is T, carried serially)
        float s = cnt;
        #pragma unroll
        for (int off = 1; off < 32; off <<= 1) {
            const float u = __shfl_up_sync(FULL, s, off);
            if (lane >= off) s += u;
        }
        const float warpTot = __shfl_sync(FULL, s, 31);

        // exp work only while e^{-beta*k} can be nonzero (fp32 underflow bound);
        // T is warp-uniform -> uniform branch, skipped after ~2 chunks
        if (beta * T < 104.f) {
            float k = T + (s - cnt);   // exclusive masked rank of my first elem
            if (m.x > 0.5f) { S += expf(fmaf(mu, e.x, -beta * k)); k += 1.f; }
            if (m.y > 0.5f) { S += expf(fmaf(mu, e.y, -beta * k)); k += 1.f; }
            if (m.z > 0.5f) { S += expf(fmaf(mu, e.z, -beta * k)); k += 1.f; }
            if (m.w > 0.5f) { S += expf(fmaf(mu, e.w, -beta * k)); }
        }
        T += warpTot;
    }

    // warp reductions (3 values, 5 rounds)
    #pragma unroll
    for (int off = 16; off; off >>= 1) {
        sumt   += __shfl_down_sync(FULL, sumt,   off);
        sumidx += __shfl_down_sync(FULL, sumidx, off);
        S      += __shfl_down_sync(FULL, S,      off);
    }

    if (lane == 0) {
        const float ll  = fmaf(mu, sumt, -beta * sumidx);
        const float emb = expf(-beta);
        // telescoped compensator: (1-e^{-b})*S - e^{mu*t0} + e^{mu*t1 - b*M}
        float comp = fmaf(1.f - emb, S, -expf(mu * t0));
        comp += expf(fmaf(mu, t1, -beta * T));   // underflows to 0 exactly, like ref
        out[row] = ll - comp / mu;
    }
}

extern "C" void kernel_launch(void* const* d_in, const int* in_sizes, int n_in,
                              void* d_out, int out_size)
{
    const float* event_times = (const float*)d_in[0];
    // d_in[1] = spatial_locations : unused by the op
    const float* input_mask  = (const float*)d_in[2];
    const float* t0          = (const float*)d_in[3];
    const float* t1          = (const float*)d_in[4];
    const float* mu_param    = (const float*)d_in[5];
    const float* beta_param  = (const float*)d_in[6];
    float* out = (float*)d_out;

    const int n_rows = out_size;  // 8192
    scpp_kernel<<<n_rows / WARPS_PER_BLOCK, 256>>>(event_times, input_mask,
                                                   t0, t1, mu_param, beta_param, out);
}

// round 6
// speedup vs baseline: 1.1799x; 1.1799x over previous
#include <cuda_runtime.h>
#include <math.h>

#define FULL 0xFFFFFFFFu
#define T_LEN 2048
#define CHUNKS 16          // 16 chunks x 128 elems = 2048
#define WPB 8              // warps per block

__global__ __launch_bounds__(256, 4)
void scpp_kernel(const float* __restrict__ event_times,
                 const float* __restrict__ input_mask,
                 const float* __restrict__ t0p,
                 const float* __restrict__ t1p,
                 const float* __restrict__ mup,
                 const float* __restrict__ betap,
                 float* __restrict__ out)
{
    const int lane = threadIdx.x & 31;
    const int wid  = threadIdx.x >> 5;
    const int row  = blockIdx.x * WPB + wid;

    const float mu   = log1pf(expf(__ldg(mup)));
    const float beta = log1pf(expf(__ldg(betap)));
    const float t0   = __ldg(t0p);
    const float t1   = __ldg(t1p);

    const size_t rbase = (size_t)row * T_LEN;
    const float4* ev = reinterpret_cast<const float4*>(event_times + rbase);
    const float4* mk = reinterpret_cast<const float4*>(input_mask  + rbase);

    float sumt = 0.f;     // sum mask * t
    float sumidx = 0.f;   // sum mask * index (integer-valued, < 2^24: exact)
    float S = 0.f;        // sum masked exp(mu*t - beta*k)
    float T = 0.f;        // running masked count (warp-uniform)

    // ================= phase 1: scan + exp, until terms underflow ============
    int i = 0;
    for (; i < CHUNKS; i++) {
        const float4 e = ev[lane + 32 * i];
        const float4 m = mk[lane + 32 * i];

        const float cnt = (m.x + m.y) + (m.z + m.w);

        sumt = fmaf(m.x, e.x, sumt);
        sumt = fmaf(m.y, e.y, sumt);
        sumt = fmaf(m.z, e.z, sumt);
        sumt = fmaf(m.w, e.w, sumt);

        const float base = (float)(128 * i + 4 * lane);
        sumidx = fmaf(cnt, base, sumidx);
        sumidx += fmaf(3.f, m.w, fmaf(2.f, m.z, m.y));

        // intra-warp inclusive scan of cnt
        float s = cnt;
        #pragma unroll
        for (int off = 1; off < 32; off <<= 1) {
            const float u = __shfl_up_sync(FULL, s, off);
            if (lane >= off) s += u;
        }

        if (beta * T < 104.f) {   // expf underflow bound
            float k = T + (s - cnt);
            if (m.x > 0.5f) { S += expf(fmaf(mu, e.x, -beta * k)); k += 1.f; }
            if (m.y > 0.5f) { S += expf(fmaf(mu, e.y, -beta * k)); k += 1.f; }
            if (m.z > 0.5f) { S += expf(fmaf(mu, e.z, -beta * k)); k += 1.f; }
            if (m.w > 0.5f) { S += expf(fmaf(mu, e.w, -beta * k)); }
        }
        T += __shfl_sync(FULL, s, 31);

        if (beta * T >= 106.f) { i++; break; }   // all remaining terms == 0.0f
    }

    // ================= phase 2: pure streaming, 4-chunk batched loads ========
    for (; i + 4 <= CHUNKS; i += 4) {
        // 8 independent LDG.128 front-batched -> MLP ~8
        const float4 e0 = ev[lane + 32 * (i + 0)];
        const float4 e1 = ev[lane + 32 * (i + 1)];
        const float4 e2 = ev[lane + 32 * (i + 2)];
        const float4 e3 = ev[lane + 32 * (i + 3)];
        const float4 m0 = mk[lane + 32 * (i + 0)];
        const float4 m1 = mk[lane + 32 * (i + 1)];
        const float4 m2 = mk[lane + 32 * (i + 2)];
        const float4 m3 = mk[lane + 32 * (i + 3)];

        const float b0 = (float)(128 * (i + 0) + 4 * lane);
        const float b1 = (float)(128 * (i + 1) + 4 * lane);
        const float b2 = (float)(128 * (i + 2) + 4 * lane);
        const float b3 = (float)(128 * (i + 3) + 4 * lane);

        sumt = fmaf(m0.x, e0.x, sumt); sumt = fmaf(m0.y, e0.y, sumt);
        sumt = fmaf(m0.z, e0.z, sumt); sumt = fmaf(m0.w, e0.w, sumt);
        sumt = fmaf(m1.x, e1.x, sumt); sumt = fmaf(m1.y, e1.y, sumt);
        sumt = fmaf(m1.z, e1.z, sumt); sumt = fmaf(m1.w, e1.w, sumt);
        sumt = fmaf(m2.x, e2.x, sumt); sumt = fmaf(m2.y, e2.y, sumt);
        sumt = fmaf(m2.z, e2.z, sumt); sumt = fmaf(m2.w, e2.w, sumt);
        sumt = fmaf(m3.x, e3.x, sumt); sumt = fmaf(m3.y, e3.y, sumt);
        sumt = fmaf(m3.z, e3.z, sumt); sumt = fmaf(m3.w, e3.w, sumt);

        const float c0 = (m0.x + m0.y) + (m0.z + m0.w);
        const float c1 = (m1.x + m1.y) + (m1.z + m1.w);
        const float c2 = (m2.x + m2.y) + (m2.z + m2.w);
        const float c3 = (m3.x + m3.y) + (m3.z + m3.w);

        sumidx = fmaf(c0, b0, sumidx);
        sumidx += fmaf(3.f, m0.w, fmaf(2.f, m0.z, m0.y));
        sumidx = fmaf(c1, b1, sumidx);
        sumidx += fmaf(3.f, m1.w, fmaf(2.f, m1.z, m1.y));
        sumidx = fmaf(c2, b2, sumidx);
        sumidx += fmaf(3.f, m2.w, fmaf(2.f, m2.z, m2.y));
        sumidx = fmaf(c3, b3, sumidx);
        sumidx += fmaf(3.f, m3.w, fmaf(2.f, m3.z, m3.y));
    }
    // tail (0-3 chunks)
    for (; i < CHUNKS; i++) {
        const float4 e = ev[lane + 32 * i];
        const float4 m = mk[lane + 32 * i];
        sumt = fmaf(m.x, e.x, sumt); sumt = fmaf(m.y, e.y, sumt);
        sumt = fmaf(m.z, e.z, sumt); sumt = fmaf(m.w, e.w, sumt);
        const float cnt = (m.x + m.y) + (m.z + m.w);
        const float base = (float)(128 * i + 4 * lane);
        sumidx = fmaf(cnt, base, sumidx);
        sumidx += fmaf(3.f, m.w, fmaf(2.f, m.z, m.y));
    }

    // ================= warp reductions =================
    #pragma unroll
    for (int off = 16; off; off >>= 1) {
        sumt   += __shfl_down_sync(FULL, sumt,   off);
        sumidx += __shfl_down_sync(FULL, sumidx, off);
        S      += __shfl_down_sync(FULL, S,      off);
    }

    if (lane == 0) {
        const float ll  = fmaf(mu, sumt, -beta * sumidx);
        const float emb = expf(-beta);
        // telescoped compensator: (1-e^{-b})*S - e^{mu*t0} + e^{mu*t1 - b*M}
        float comp = fmaf(1.f - emb, S, -expf(mu * t0));
        comp += expf(fmaf(mu, t1, -beta * T));   // exact 0 when phase-1 broke out
        out[row] = ll - comp / mu;
    }
}

extern "C" void kernel_launch(void* const* d_in, const int* in_sizes, int n_in,
                              void* d_out, int out_size)
{
    const float* event_times = (const float*)d_in[0];
    // d_in[1] = spatial_locations : unused by the op
    const float* input_mask  = (const float*)d_in[2];
    const float* t0          = (const float*)d_in[3];
    const float* t1          = (const float*)d_in[4];
    const float* mu_param    = (const float*)d_in[5];
    const float* beta_param  = (const float*)d_in[6];
    float* out = (float*)d_out;

    const int n_rows = out_size;  // 8192
    scpp_kernel<<<n_rows / WPB, 256>>>(event_times, input_mask,
                                       t0, t1, mu_param, beta_param, out);
}